// round 12
// baseline (speedup 1.0000x reference)
#include <cuda_runtime.h>
#include <cuda_fp16.h>
#include <cstdint>

#define BATCH   16
#define NNODES  10000
#define HDIM    128
#define NEDGES  320000
#define NROWS   (BATCH * NNODES)      // 160000
#define NTILES  (NROWS / 128)         // 1250

// ---------------- scratch (device globals; no allocation allowed) ----------
__device__ int    g_counts[NNODES];
__device__ int    g_offsets[NNODES + 1];
__device__ int    g_cursor[NNODES];
__device__ int    g_csr[NEDGES];
__device__ int    g_tileflag[NTILES];   // 1 = tile gathered
__device__ int    g_gctr;               // gather tile counter
__device__ __half g_emb16[(size_t)NROWS * HDIM];   // 41 MB fp16 copy
__device__ __half g_nbr16[(size_t)NROWS * HDIM];   // 41 MB neighbor sums
__device__ __half g_w1_16[256 * 128];
__device__ __half g_w2_16[128 * 128];

// ---------------- helpers -----------------------------------------------------
__device__ __forceinline__ uint32_t smem_u32(const void* p) {
    uint32_t a;
    asm("{ .reg .u64 t; cvta.to.shared.u64 t, %1; cvt.u32.u64 %0, t; }"
        : "=r"(a) : "l"(p));
    return a;
}
__device__ __forceinline__ void ldsm4(uint32_t* r, uint32_t a) {
    asm volatile("ldmatrix.sync.aligned.m8n8.x4.shared.b16 {%0,%1,%2,%3}, [%4];"
                 : "=r"(r[0]), "=r"(r[1]), "=r"(r[2]), "=r"(r[3]) : "r"(a));
}
__device__ __forceinline__ void ldsm4t(uint32_t* r, uint32_t a) {
    asm volatile("ldmatrix.sync.aligned.m8n8.x4.trans.shared.b16 {%0,%1,%2,%3}, [%4];"
                 : "=r"(r[0]), "=r"(r[1]), "=r"(r[2]), "=r"(r[3]) : "r"(a));
}
__device__ __forceinline__ void mma16816(float* c, const uint32_t* a,
                                         uint32_t b0, uint32_t b1) {
    asm volatile(
        "mma.sync.aligned.m16n8k16.row.col.f32.f16.f16.f32 "
        "{%0,%1,%2,%3}, {%4,%5,%6,%7}, {%8,%9}, {%0,%1,%2,%3};"
        : "+f"(c[0]), "+f"(c[1]), "+f"(c[2]), "+f"(c[3])
        : "r"(a[0]), "r"(a[1]), "r"(a[2]), "r"(a[3]), "r"(b0), "r"(b1));
}
// one warp gathers one row into g_nbr16 (fp32 accumulate over CSR neighbors)
template <int UNROLL>
__device__ __forceinline__ void gather_row(int row, int lane) {
    int b = row / NNODES;
    int n = row - b * NNODES;
    const __half* embB = g_emb16 + (size_t)b * NNODES * 128 + lane * 4;
    int beg = g_offsets[n], end = g_offsets[n + 1];
    float4 acc = make_float4(0.f, 0.f, 0.f, 0.f);
    int i = beg;
    for (; i + UNROLL <= end; i += UNROLL) {
        uint2 p[UNROLL];
#pragma unroll
        for (int q = 0; q < UNROLL; q++)
            p[q] = *(const uint2*)(embB + (size_t)__ldg(g_csr + i + q) * 128);
#pragma unroll
        for (int q = 0; q < UNROLL; q++) {
            float2 f0 = __half22float2(*(__half2*)&p[q].x);
            float2 f1 = __half22float2(*(__half2*)&p[q].y);
            acc.x += f0.x; acc.y += f0.y; acc.z += f1.x; acc.w += f1.y;
        }
    }
    for (; i < end; i++) {
        uint2 p = *(const uint2*)(embB + (size_t)__ldg(g_csr + i) * 128);
        float2 f0 = __half22float2(*(__half2*)&p.x);
        float2 f1 = __half22float2(*(__half2*)&p.y);
        acc.x += f0.x; acc.y += f0.y; acc.z += f1.x; acc.w += f1.y;
    }
    __half2 h0 = __floats2half2_rn(acc.x, acc.y);
    __half2 h1 = __floats2half2_rn(acc.z, acc.w);
    *(uint2*)(g_nbr16 + (size_t)row * 128 + lane * 4) =
        make_uint2(*(uint32_t*)&h0, *(uint32_t*)&h1);
}

// ---------------- zero pass -----------------------------------------------------
__global__ void zero_k() {
    int i = blockIdx.x * blockDim.x + threadIdx.x;
    if (i < NNODES) g_counts[i] = 0;
    if (i < NTILES) g_tileflag[i] = 0;
    if (i == 0) g_gctr = 0;
}

// ---------------- emb fp32 -> fp16 copy, hist fused in ------------------------
__global__ __launch_bounds__(256)
void econv_hist_k(const float* __restrict__ emb, const int* __restrict__ edge) {
    size_t gid = (size_t)blockIdx.x * 256 + threadIdx.x;
    if (blockIdx.x < NEDGES / 256)
        atomicAdd(&g_counts[edge[NEDGES + gid]], 1);
    const float4* s = (const float4*)(emb) + gid * 2;
    float4 a = s[0], b = s[1];
    __half2 h0 = __float22half2_rn(make_float2(a.x, a.y));
    __half2 h1 = __float22half2_rn(make_float2(a.z, a.w));
    __half2 h2 = __float22half2_rn(make_float2(b.x, b.y));
    __half2 h3 = __float22half2_rn(make_float2(b.z, b.w));
    uint4 o;
    o.x = *(uint32_t*)&h0; o.y = *(uint32_t*)&h1;
    o.z = *(uint32_t*)&h2; o.w = *(uint32_t*)&h3;
    *((uint4*)g_emb16 + gid) = o;
}

__global__ void scan_k() {
    __shared__ int part[1024];
    const int CH = 10;
    int t = threadIdx.x;
    int local[CH];
    int s = 0;
#pragma unroll
    for (int i = 0; i < CH; i++) {
        int idx = t * CH + i;
        int v = (idx < NNODES) ? g_counts[idx] : 0;
        local[i] = s;
        s += v;
    }
    part[t] = s;
    __syncthreads();
    for (int off = 1; off < 1024; off <<= 1) {
        int v = (t >= off) ? part[t - off] : 0;
        __syncthreads();
        part[t] += v;
        __syncthreads();
    }
    int excl = (t == 0) ? 0 : part[t - 1];
#pragma unroll
    for (int i = 0; i < CH; i++) {
        int idx = t * CH + i;
        if (idx < NNODES) {
            int o = excl + local[i];
            g_offsets[idx] = o;
            g_cursor[idx]  = o;
        }
    }
    if (t == 1023) g_offsets[NNODES] = part[1023];
}
__global__ void scatter_k(const int* __restrict__ edge) {
    int e = blockIdx.x * blockDim.x + threadIdx.x;
    if (e < NEDGES) {
        int d = edge[NEDGES + e];
        int p = atomicAdd(&g_cursor[d], 1);
        g_csr[p] = edge[e];
    }
}

// ---------------- weight fp32 -> fp16 ------------------------------------------
__global__ void wconv_k(const float* __restrict__ W, __half* o16, int total) {
    int i = blockIdx.x * blockDim.x + threadIdx.x;
    if (i < total) o16[i] = __float2half_rn(W[i]);
}

// ---------------- persistent gather: 2 CTAs/SM, tile per iteration --------------
// 8 warps x 16 rows = 128-row tile per CTA loop iteration.
// ≤64 regs (launch_bounds 256,4) so 2 CTAs use 32K regs; consumer's 32K also fits.
__global__ __launch_bounds__(256, 4)
void gather_k() {
    __shared__ int s_t;
    int wid  = threadIdx.x >> 5;
    int lane = threadIdx.x & 31;
    while (true) {
        if (threadIdx.x == 0) s_t = atomicAdd(&g_gctr, 1);
        __syncthreads();
        int tile = s_t;
        if (tile >= NTILES) return;
        int rowBase = tile * 128;
#pragma unroll 1
        for (int rr = 0; rr < 16; rr++)
            gather_row<16>(rowBase + wid * 16 + rr, lane);
        __threadfence();     // each thread releases its own writes
        __syncthreads();     // all fences ordered before the flag
        if (threadIdx.x == 0) atomicExch(&g_tileflag[tile], 1);
    }
}

// ---------------- persistent consumer: GEMM1+GEMM2 per tile --------------------
// smem (160KB): [0,64K) W1 | [64K,96K) W2 | [96K,160K) ctx 4x16KB; h->chunks 0-1
// launch_bounds(256,2) caps regs at 128/thread -> 32K regs; gather co-resides.
#define SM_W1   0
#define SM_W2   65536
#define SM_BUF  98304
#define SMEM_FUSED 163840

__global__ __launch_bounds__(256, 2)
void consumer_k(const float* __restrict__ bias1, const float* __restrict__ bias2,
                const int* __restrict__ mask, const float* __restrict__ emb32,
                float* __restrict__ outp) {
    extern __shared__ __align__(128) char smem[];
    __shared__ int s_need;
    int tid  = threadIdx.x;
    int lane = tid & 31;
    int wid  = tid >> 5;
    uint32_t sb = smem_u32(smem);

    // W1 + W2 once, swizzled: off(k,c16)=k*256+((c^(k&7))<<4)
#pragma unroll
    for (int i = 0; i < 16; i++) {
        int idx = i * 256 + tid;
        int k = idx >> 4, c = idx & 15;
        uint32_t off = (uint32_t)(k * 256 + ((c ^ (k & 7)) << 4));
        *(uint4*)(smem + SM_W1 + off) =
            *(const uint4*)(g_w1_16 + (size_t)k * 128 + c * 8);
    }
#pragma unroll
    for (int i = 0; i < 8; i++) {
        int idx = i * 256 + tid;
        int k = idx >> 4, c = idx & 15;
        uint32_t off = (uint32_t)(k * 256 + ((c ^ (k & 7)) << 4));
        *(uint4*)(smem + SM_W2 + off) =
            *(const uint4*)(g_w2_16 + (size_t)k * 128 + c * 8);
    }
    __syncthreads();

    int wm = wid & 3, wn = wid >> 2;
    int g = lane >> 2, tig = lane & 3;
    float acc[2][8][4];
    uint32_t bufu = sb + SM_BUF;
    char* buf = smem + SM_BUF;

    auto stage = [&](const __half* src, int rowBase, int kb, int slot) {
        char* dst = buf + slot * 16384;
#pragma unroll
        for (int it2 = 0; it2 < 4; it2++) {
            int idx = it2 * 256 + tid;
            int r = idx >> 3, c = idx & 7;
            uint32_t off = (uint32_t)(r * 128 + ((c ^ (r & 7)) << 4));
            *(uint4*)(dst + off) =
                *(const uint4*)(src + (size_t)(rowBase + r) * 128 + kb + c * 8);
        }
    };
    auto mma_block = [&](uint32_t aB, uint32_t bB, int kk, int kAbs) {
        uint32_t aF[2][4], bF[4][4];
#pragma unroll
        for (int mi = 0; mi < 2; mi++) {
            int r = wm * 32 + mi * 16 + (lane & 15);
            int c = kk * 2 + (lane >> 4);
            uint32_t off = (uint32_t)(r * 128 + ((c ^ (r & 7)) << 4));
            ldsm4(aF[mi], aB + off);
        }
#pragma unroll
        for (int q = 0; q < 4; q++) {
            int k = kAbs + (lane & 15);
            int c = (wn * 64 + q * 16 + ((lane >> 4) << 3)) >> 3;
            uint32_t boff = (uint32_t)(k * 256 + ((c ^ (k & 7)) << 4));
            ldsm4t(bF[q], bB + boff);
        }
#pragma unroll
        for (int mi = 0; mi < 2; mi++)
#pragma unroll
            for (int n8 = 0; n8 < 8; n8++)
                mma16816(acc[mi][n8], aF[mi],
                         bF[n8 >> 1][(n8 & 1) * 2],
                         bF[n8 >> 1][(n8 & 1) * 2 + 1]);
    };

    for (int tile = blockIdx.x; tile < NTILES; tile += gridDim.x) {
        int rowBase = tile * 128;

        // emb chunks first (flag-independent)
        stage(g_emb16, rowBase, 0, 2);
        stage(g_emb16, rowBase, 64, 3);

        // wait for gather of this tile; bounded spin + bit-identical self-gather
        if (tid == 0) {
            int v = 0;
            for (int spin = 0; spin < 4000; ++spin) {
                asm volatile("ld.acquire.gpu.global.b32 %0, [%1];"
                             : "=r"(v) : "l"(&g_tileflag[tile]) : "memory");
                if (v) break;
                __nanosleep(64);
            }
            s_need = (v == 0);
        }
        __syncthreads();
        if (s_need) {
            for (int rr = 0; rr < 16; rr++)
                gather_row<16>(rowBase + wid * 16 + rr, lane);
            __syncthreads();
        }

        stage(g_nbr16, rowBase, 0, 0);
        stage(g_nbr16, rowBase, 64, 1);
        __syncthreads();

        // ---- GEMM1: K=256 over 4 resident chunks ----
#pragma unroll
        for (int mi = 0; mi < 2; mi++)
#pragma unroll
            for (int n8 = 0; n8 < 8; n8++)
#pragma unroll
                for (int q = 0; q < 4; q++) acc[mi][n8][q] = 0.f;
#pragma unroll
        for (int ch = 0; ch < 4; ch++)
#pragma unroll
            for (int kk = 0; kk < 4; kk++)
                mma_block(bufu + ch * 16384, sb + SM_W1, kk, ch * 64 + kk * 16);
        __syncthreads();

        // ---- epilogue1: relu+bias -> h fp16 into chunks 0-1 ----
#pragma unroll
        for (int mi = 0; mi < 2; mi++) {
#pragma unroll
            for (int half = 0; half < 2; half++) {
                int rl = wm * 32 + mi * 16 + g + half * 8;
#pragma unroll
                for (int n8 = 0; n8 < 8; n8++) {
                    int cidx = wn * 64 + n8 * 8 + tig * 2;
                    float x0 = fmaxf(acc[mi][n8][half * 2 + 0] + __ldg(bias1 + cidx), 0.f);
                    float x1 = fmaxf(acc[mi][n8][half * 2 + 1] + __ldg(bias1 + cidx + 1), 0.f);
                    __half2 hv = __floats2half2_rn(x0, x1);
                    uint32_t off = (uint32_t)(rl * 128 + ((n8 ^ (rl & 7)) << 4) + tig * 4);
                    *(uint32_t*)(buf + wn * 16384 + off) = *(uint32_t*)&hv;
                }
            }
        }
        __syncthreads();

        // ---- GEMM2: K=128, A = h chunks 0-1 ----
#pragma unroll
        for (int mi = 0; mi < 2; mi++)
#pragma unroll
            for (int n8 = 0; n8 < 8; n8++)
#pragma unroll
                for (int q = 0; q < 4; q++) acc[mi][n8][q] = 0.f;
#pragma unroll
        for (int ch = 0; ch < 2; ch++)
#pragma unroll
            for (int kk = 0; kk < 4; kk++)
                mma_block(bufu + ch * 16384, sb + SM_W2, kk, ch * 64 + kk * 16);

        // ---- epilogue2: bias + mask select -> out ----
#pragma unroll
        for (int mi = 0; mi < 2; mi++) {
#pragma unroll
            for (int half = 0; half < 2; half++) {
                int r = rowBase + wm * 32 + mi * 16 + g + half * 8;
                bool doImp = (mask[r] != 0);
#pragma unroll
                for (int n8 = 0; n8 < 8; n8++) {
                    int cidx = wn * 64 + n8 * 8 + tig * 2;
                    float2 v;
                    v.x = acc[mi][n8][half * 2 + 0] + __ldg(bias2 + cidx);
                    v.y = acc[mi][n8][half * 2 + 1] + __ldg(bias2 + cidx + 1);
                    if (!doImp)
                        v = *(const float2*)(emb32 + (size_t)r * 128 + cidx);
                    *(float2*)(outp + (size_t)r * 128 + cidx) = v;
                }
            }
        }
        __syncthreads();   // buf reused next tile
    }
}

// ---------------- launch -------------------------------------------------------
extern "C" void kernel_launch(void* const* d_in, const int* in_sizes, int n_in,
                              void* d_out, int out_size) {
    const float* emb  = (const float*)d_in[0];
    const int*   mask = (const int*)d_in[1];
    const int*   edge = (const int*)d_in[2];
    const float* W1   = (const float*)d_in[3];
    const float* b1   = (const float*)d_in[4];
    const float* W2   = (const float*)d_in[5];
    const float* b2   = (const float*)d_in[6];
    float*       out  = (float*)d_out;

    cudaFuncSetAttribute(consumer_k,
                         cudaFuncAttributeMaxDynamicSharedMemorySize, SMEM_FUSED);
    int dev = 0, sms = 148;
    cudaGetDevice(&dev);
    cudaDeviceGetAttribute(&sms, cudaDevAttrMultiProcessorCount, dev);
    int csms = (sms > NTILES) ? NTILES : sms;

    // ---- prepass (capture stream) ----
    zero_k<<<(NNODES + 255) / 256, 256>>>();
    econv_hist_k<<<NROWS * HDIM / (256 * 8), 256>>>(emb, edge);
    scan_k<<<1, 1024>>>();
    scatter_k<<<(NEDGES + 255) / 256, 256>>>(edge);

    __half *w1p, *w2p;
    cudaGetSymbolAddress((void**)&w1p, g_w1_16);
    cudaGetSymbolAddress((void**)&w2p, g_w2_16);
    wconv_k<<<128, 256>>>(W1, w1p, 256 * 128);
    wconv_k<<<64, 256>>>(W2, w2p, 128 * 128);

    // ---- fork: gather (2 CTAs/SM, persistent) || consumer (1 CTA/SM) ----
    // Stream/events intentionally not destroyed (capture-participating).
    cudaStream_t s2;
    cudaEvent_t evF, evJ;
    bool forked = true;
    if (cudaStreamCreateWithFlags(&s2, cudaStreamNonBlocking) != cudaSuccess)
        forked = false;
    if (forked && cudaEventCreateWithFlags(&evF, cudaEventDisableTiming) != cudaSuccess)
        forked = false;
    if (forked && cudaEventCreateWithFlags(&evJ, cudaEventDisableTiming) != cudaSuccess)
        forked = false;
    if (forked && cudaEventRecord(evF, 0) != cudaSuccess)
        forked = false;
    if (forked && cudaStreamWaitEvent(s2, evF, 0) != cudaSuccess)
        forked = false;

    if (forked) {
        gather_k<<<2 * sms, 256, 0, s2>>>();
        bool joined = (cudaEventRecord(evJ, s2) == cudaSuccess);
        consumer_k<<<csms, 256, SMEM_FUSED>>>(b1, b2, mask, emb, out);
        if (joined) cudaStreamWaitEvent(0, evJ, 0);
    } else {
        // serial fallback: gather then consumer (flags ready -> no spins)
        gather_k<<<2 * sms, 256>>>();
        consumer_k<<<csms, 256, SMEM_FUSED>>>(b1, b2, mask, emb, out);
    }
}

// round 16
// speedup vs baseline: 1.4712x; 1.4712x over previous
#include <cuda_runtime.h>
#include <cuda_fp16.h>
#include <cstdint>

#define BATCH   16
#define NNODES  10000
#define HDIM    128
#define NEDGES  320000
#define NROWS   (BATCH * NNODES)      // 160000

// ---------------- scratch (device globals; no allocation allowed) ----------
__device__ int    g_counts[NNODES];
__device__ int    g_offsets[NNODES + 1];
__device__ int    g_cursor[NNODES];
__device__ int    g_csr[NEDGES];
__device__ int    g_mrows[NROWS];        // compacted masked row indices
__device__ int    g_mcount;
__device__ __half g_emb16[(size_t)NROWS * HDIM];   // 41 MB fp16 copy
__device__ __half g_nbr16[(size_t)NROWS * HDIM];   // compacted neighbor sums
__device__ __half g_w1_16[256 * 128];
__device__ __half g_w2_16[128 * 128];

// ---------------- helpers -----------------------------------------------------
__device__ __forceinline__ uint32_t smem_u32(const void* p) {
    uint32_t a;
    asm("{ .reg .u64 t; cvta.to.shared.u64 t, %1; cvt.u32.u64 %0, t; }"
        : "=r"(a) : "l"(p));
    return a;
}
__device__ __forceinline__ void ldsm4(uint32_t* r, uint32_t a) {
    asm volatile("ldmatrix.sync.aligned.m8n8.x4.shared.b16 {%0,%1,%2,%3}, [%4];"
                 : "=r"(r[0]), "=r"(r[1]), "=r"(r[2]), "=r"(r[3]) : "r"(a));
}
__device__ __forceinline__ void ldsm4t(uint32_t* r, uint32_t a) {
    asm volatile("ldmatrix.sync.aligned.m8n8.x4.trans.shared.b16 {%0,%1,%2,%3}, [%4];"
                 : "=r"(r[0]), "=r"(r[1]), "=r"(r[2]), "=r"(r[3]) : "r"(a));
}
__device__ __forceinline__ void mma16816(float* c, const uint32_t* a,
                                         uint32_t b0, uint32_t b1) {
    asm volatile(
        "mma.sync.aligned.m16n8k16.row.col.f32.f16.f16.f32 "
        "{%0,%1,%2,%3}, {%4,%5,%6,%7}, {%8,%9}, {%0,%1,%2,%3};"
        : "+f"(c[0]), "+f"(c[1]), "+f"(c[2]), "+f"(c[3])
        : "r"(a[0]), "r"(a[1]), "r"(a[2]), "r"(a[3]), "r"(b0), "r"(b1));
}

// ---------------- zero pass -----------------------------------------------------
__global__ void zero_k() {
    int i = blockIdx.x * blockDim.x + threadIdx.x;
    if (i < NNODES) g_counts[i] = 0;
    if (i == 0) g_mcount = 0;
}

// ---------------- emb fp32 -> fp16 copy, hist fused in ------------------------
__global__ __launch_bounds__(256)
void econv_hist_k(const float* __restrict__ emb, const int* __restrict__ edge) {
    size_t gid = (size_t)blockIdx.x * 256 + threadIdx.x;
    if (blockIdx.x < NEDGES / 256)
        atomicAdd(&g_counts[edge[NEDGES + gid]], 1);
    const float4* s = (const float4*)(emb) + gid * 2;
    float4 a = s[0], b = s[1];
    __half2 h0 = __float22half2_rn(make_float2(a.x, a.y));
    __half2 h1 = __float22half2_rn(make_float2(a.z, a.w));
    __half2 h2 = __float22half2_rn(make_float2(b.x, b.y));
    __half2 h3 = __float22half2_rn(make_float2(b.z, b.w));
    uint4 o;
    o.x = *(uint32_t*)&h0; o.y = *(uint32_t*)&h1;
    o.z = *(uint32_t*)&h2; o.w = *(uint32_t*)&h3;
    *((uint4*)g_emb16 + gid) = o;
}

__global__ void scan_k() {
    __shared__ int part[1024];
    const int CH = 10;
    int t = threadIdx.x;
    int local[CH];
    int s = 0;
#pragma unroll
    for (int i = 0; i < CH; i++) {
        int idx = t * CH + i;
        int v = (idx < NNODES) ? g_counts[idx] : 0;
        local[i] = s;
        s += v;
    }
    part[t] = s;
    __syncthreads();
    for (int off = 1; off < 1024; off <<= 1) {
        int v = (t >= off) ? part[t - off] : 0;
        __syncthreads();
        part[t] += v;
        __syncthreads();
    }
    int excl = (t == 0) ? 0 : part[t - 1];
#pragma unroll
    for (int i = 0; i < CH; i++) {
        int idx = t * CH + i;
        if (idx < NNODES) {
            int o = excl + local[i];
            g_offsets[idx] = o;
            g_cursor[idx]  = o;
        }
    }
    if (t == 1023) g_offsets[NNODES] = part[1023];
}
__global__ void scatter_k(const int* __restrict__ edge) {
    int e = blockIdx.x * blockDim.x + threadIdx.x;
    if (e < NEDGES) {
        int d = edge[NEDGES + e];
        int p = atomicAdd(&g_cursor[d], 1);
        g_csr[p] = edge[e];
    }
}

// ---------------- weight fp32 -> fp16 ------------------------------------------
__global__ void wconv_k(const float* __restrict__ W, __half* o16, int total) {
    int i = blockIdx.x * blockDim.x + threadIdx.x;
    if (i < total) o16[i] = __float2half_rn(W[i]);
}

// ---------------- mask compaction ----------------------------------------------
__global__ void compact_k(const int* __restrict__ mask) {
    int i = blockIdx.x * blockDim.x + threadIdx.x;
    if (i < NROWS && mask[i] != 0) {
        int p = atomicAdd(&g_mcount, 1);
        g_mrows[p] = i;
    }
}

// ---------------- pass-through copy for unmasked rows --------------------------
__global__ __launch_bounds__(256)
void passthru_k(const float* __restrict__ emb, const int* __restrict__ mask,
                float* __restrict__ outp) {
    size_t idx = (size_t)blockIdx.x * 256 + threadIdx.x;   // one float4
    int row = (int)(idx >> 5);
    if (mask[row] == 0)
        ((float4*)outp)[idx] = ((const float4*)emb)[idx];
}

// ---------------- gather (masked rows only, compacted output) ------------------
// high-occupancy R5 shape: warp per compact index, unroll-16
__global__ __launch_bounds__(256, 4)
void gather_k() {
    int wid  = threadIdx.x >> 5;
    int lane = threadIdx.x & 31;
    int ci   = blockIdx.x * 8 + wid;
    if (ci >= g_mcount) return;
    int row = g_mrows[ci];
    int b = row / NNODES;
    int n = row - b * NNODES;
    const __half* embB = g_emb16 + (size_t)b * NNODES * 128 + lane * 4;
    int beg = g_offsets[n], end = g_offsets[n + 1];
    float4 acc = make_float4(0.f, 0.f, 0.f, 0.f);
    int i = beg;
    for (; i + 16 <= end; i += 16) {
        uint2 p[16];
#pragma unroll
        for (int q = 0; q < 16; q++)
            p[q] = *(const uint2*)(embB + (size_t)__ldg(g_csr + i + q) * 128);
#pragma unroll
        for (int q = 0; q < 16; q++) {
            float2 f0 = __half22float2(*(__half2*)&p[q].x);
            float2 f1 = __half22float2(*(__half2*)&p[q].y);
            acc.x += f0.x; acc.y += f0.y; acc.z += f1.x; acc.w += f1.y;
        }
    }
    for (; i < end; i++) {
        uint2 p = *(const uint2*)(embB + (size_t)__ldg(g_csr + i) * 128);
        float2 f0 = __half22float2(*(__half2*)&p.x);
        float2 f1 = __half22float2(*(__half2*)&p.y);
        acc.x += f0.x; acc.y += f0.y; acc.z += f1.x; acc.w += f1.y;
    }
    __half2 h0 = __floats2half2_rn(acc.x, acc.y);
    __half2 h1 = __floats2half2_rn(acc.z, acc.w);
    *(uint2*)(g_nbr16 + (size_t)ci * 128 + lane * 4) =
        make_uint2(*(uint32_t*)&h0, *(uint32_t*)&h1);
}

// ---------------- consumer: GEMM1+GEMM2 on compacted masked rows ----------------
// smem: [0,64K) W1 | [64K,96K) W2 | [96K,160K) ctx 4x16KB | [160K,+512) row tbl
#define SM_W1   0
#define SM_W2   65536
#define SM_BUF  98304
#define SM_ROWS 163840
#define SMEM_FUSED 164864

__global__ __launch_bounds__(256, 1)
void consumer_k(const float* __restrict__ bias1, const float* __restrict__ bias2,
                float* __restrict__ outp) {
    extern __shared__ __align__(128) char smem[];
    int tid  = threadIdx.x;
    int lane = tid & 31;
    int wid  = tid >> 5;
    uint32_t sb = smem_u32(smem);
    int* s_rows = (int*)(smem + SM_ROWS);

    int mcount = *(volatile int*)&g_mcount;
    int ntiles = (mcount + 127) >> 7;

    // W1 + W2 once, swizzled: off(k,c16)=k*256+((c^(k&7))<<4)
#pragma unroll
    for (int i = 0; i < 16; i++) {
        int idx = i * 256 + tid;
        int k = idx >> 4, c = idx & 15;
        uint32_t off = (uint32_t)(k * 256 + ((c ^ (k & 7)) << 4));
        *(uint4*)(smem + SM_W1 + off) =
            *(const uint4*)(g_w1_16 + (size_t)k * 128 + c * 8);
    }
#pragma unroll
    for (int i = 0; i < 8; i++) {
        int idx = i * 256 + tid;
        int k = idx >> 4, c = idx & 15;
        uint32_t off = (uint32_t)(k * 256 + ((c ^ (k & 7)) << 4));
        *(uint4*)(smem + SM_W2 + off) =
            *(const uint4*)(g_w2_16 + (size_t)k * 128 + c * 8);
    }
    __syncthreads();

    int wm = wid & 3, wn = wid >> 2;
    int g = lane >> 2, tig = lane & 3;
    float acc[2][8][4];
    uint32_t bufu = sb + SM_BUF;
    char* buf = smem + SM_BUF;

    auto mma_block = [&](uint32_t aB, uint32_t bB, int kk, int kAbs) {
        uint32_t aF[2][4], bF[4][4];
#pragma unroll
        for (int mi = 0; mi < 2; mi++) {
            int r = wm * 32 + mi * 16 + (lane & 15);
            int c = kk * 2 + (lane >> 4);
            uint32_t off = (uint32_t)(r * 128 + ((c ^ (r & 7)) << 4));
            ldsm4(aF[mi], aB + off);
        }
#pragma unroll
        for (int q = 0; q < 4; q++) {
            int k = kAbs + (lane & 15);
            int c = (wn * 64 + q * 16 + ((lane >> 4) << 3)) >> 3;
            uint32_t boff = (uint32_t)(k * 256 + ((c ^ (k & 7)) << 4));
            ldsm4t(bF[q], bB + boff);
        }
#pragma unroll
        for (int mi = 0; mi < 2; mi++)
#pragma unroll
            for (int n8 = 0; n8 < 8; n8++)
                mma16816(acc[mi][n8], aF[mi],
                         bF[n8 >> 1][(n8 & 1) * 2],
                         bF[n8 >> 1][(n8 & 1) * 2 + 1]);
    };

    for (int tile = blockIdx.x; tile < ntiles; tile += gridDim.x) {
        int base = tile * 128;

        // row table (clamped for tail tile)
        if (tid < 128) {
            int gi = base + tid;
            s_rows[tid] = g_mrows[(gi < mcount) ? gi : (mcount - 1)];
        }
        __syncthreads();

        // stage nbr (compacted, contiguous) -> chunks 0-1
#pragma unroll
        for (int it2 = 0; it2 < 8; it2++) {
            int idx = it2 * 256 + tid;               // 2048 chunks (128x128)
            int r = idx >> 4, c = idx & 15;
            uint32_t off = (uint32_t)(r * 128 + (((c & 7) ^ (r & 7)) << 4));
            *(uint4*)(buf + (c >> 3) * 16384 + off) =
                *(const uint4*)(g_nbr16 + ((size_t)base + r) * 128 + c * 8);
        }
        // stage emb (indirect rows) -> chunks 2-3
#pragma unroll
        for (int it2 = 0; it2 < 8; it2++) {
            int idx = it2 * 256 + tid;
            int r = idx >> 4, c = idx & 15;
            uint32_t off = (uint32_t)(r * 128 + (((c & 7) ^ (r & 7)) << 4));
            *(uint4*)(buf + (2 + (c >> 3)) * 16384 + off) =
                *(const uint4*)(g_emb16 + (size_t)s_rows[r] * 128 + c * 8);
        }
        __syncthreads();

        // ---- GEMM1: K=256 over 4 resident chunks ----
#pragma unroll
        for (int mi = 0; mi < 2; mi++)
#pragma unroll
            for (int n8 = 0; n8 < 8; n8++)
#pragma unroll
                for (int q = 0; q < 4; q++) acc[mi][n8][q] = 0.f;
#pragma unroll
        for (int ch = 0; ch < 4; ch++)
#pragma unroll
            for (int kk = 0; kk < 4; kk++)
                mma_block(bufu + ch * 16384, sb + SM_W1, kk, ch * 64 + kk * 16);
        __syncthreads();

        // ---- epilogue1: relu+bias -> h fp16 into chunks 0-1 ----
#pragma unroll
        for (int mi = 0; mi < 2; mi++) {
#pragma unroll
            for (int half = 0; half < 2; half++) {
                int rl = wm * 32 + mi * 16 + g + half * 8;
#pragma unroll
                for (int n8 = 0; n8 < 8; n8++) {
                    int cidx = wn * 64 + n8 * 8 + tig * 2;
                    float x0 = fmaxf(acc[mi][n8][half * 2 + 0] + __ldg(bias1 + cidx), 0.f);
                    float x1 = fmaxf(acc[mi][n8][half * 2 + 1] + __ldg(bias1 + cidx + 1), 0.f);
                    __half2 hv = __floats2half2_rn(x0, x1);
                    uint32_t off = (uint32_t)(rl * 128 + ((n8 ^ (rl & 7)) << 4) + tig * 4);
                    *(uint32_t*)(buf + wn * 16384 + off) = *(uint32_t*)&hv;
                }
            }
        }
        __syncthreads();

        // ---- GEMM2: K=128, A = h chunks 0-1 ----
#pragma unroll
        for (int mi = 0; mi < 2; mi++)
#pragma unroll
            for (int n8 = 0; n8 < 8; n8++)
#pragma unroll
                for (int q = 0; q < 4; q++) acc[mi][n8][q] = 0.f;
#pragma unroll
        for (int ch = 0; ch < 2; ch++)
#pragma unroll
            for (int kk = 0; kk < 4; kk++)
                mma_block(bufu + ch * 16384, sb + SM_W2, kk, ch * 64 + kk * 16);

        // ---- epilogue2: bias -> out (valid rows only; all are masked) ----
#pragma unroll
        for (int mi = 0; mi < 2; mi++) {
#pragma unroll
            for (int half = 0; half < 2; half++) {
                int rl = wm * 32 + mi * 16 + g + half * 8;
                if (base + rl < mcount) {
                    size_t r = (size_t)s_rows[rl];
#pragma unroll
                    for (int n8 = 0; n8 < 8; n8++) {
                        int cidx = wn * 64 + n8 * 8 + tig * 2;
                        float2 v;
                        v.x = acc[mi][n8][half * 2 + 0] + __ldg(bias2 + cidx);
                        v.y = acc[mi][n8][half * 2 + 1] + __ldg(bias2 + cidx + 1);
                        *(float2*)(outp + r * 128 + cidx) = v;
                    }
                }
            }
        }
        __syncthreads();   // buf + s_rows reused next tile
    }
}

// ---------------- launch -------------------------------------------------------
extern "C" void kernel_launch(void* const* d_in, const int* in_sizes, int n_in,
                              void* d_out, int out_size) {
    const float* emb  = (const float*)d_in[0];
    const int*   mask = (const int*)d_in[1];
    const int*   edge = (const int*)d_in[2];
    const float* W1   = (const float*)d_in[3];
    const float* b1   = (const float*)d_in[4];
    const float* W2   = (const float*)d_in[5];
    const float* b2   = (const float*)d_in[6];
    float*       out  = (float*)d_out;

    cudaFuncSetAttribute(consumer_k,
                         cudaFuncAttributeMaxDynamicSharedMemorySize, SMEM_FUSED);
    int dev = 0, sms = 148;
    cudaGetDevice(&dev);
    cudaDeviceGetAttribute(&sms, cudaDevAttrMultiProcessorCount, dev);

    // prepass: zero, emb->fp16 + hist, scan, scatter, weights, compact, passthru
    zero_k<<<(NNODES + 255) / 256, 256>>>();
    econv_hist_k<<<NROWS * HDIM / (256 * 8), 256>>>(emb, edge);
    scan_k<<<1, 1024>>>();
    scatter_k<<<(NEDGES + 255) / 256, 256>>>(edge);

    __half *w1p, *w2p;
    cudaGetSymbolAddress((void**)&w1p, g_w1_16);
    cudaGetSymbolAddress((void**)&w2p, g_w2_16);
    wconv_k<<<128, 256>>>(W1, w1p, 256 * 128);
    wconv_k<<<64, 256>>>(W2, w2p, 128 * 128);

    compact_k<<<(NROWS + 255) / 256, 256>>>(mask);
    passthru_k<<<NROWS * 32 / 256, 256>>>(emb, mask, out);

    // gather masked rows (worst-case grid; idle warps exit on g_mcount)
    gather_k<<<NROWS / 8, 256>>>();

    // GEMM1+GEMM2 on compacted rows
    consumer_k<<<sms, 256, SMEM_FUSED>>>(b1, b2, out);
}